// round 12
// baseline (speedup 1.0000x reference)
#include <cuda_runtime.h>
#include <cstdint>

#define T_STEPS 16384
#define FULLMASK 0xffffffffu

// Per-step blob, 36 floats per lane (32 lanes) = 1152 floats = 4608 B/step.
// Lane L (n = L&15, hi = L>=16):
//  f[0..7]   : A[n][m] for m in lo?0..7:8..15      (hg partial)
//  f[8..23]  : K1 col n (lo) / K3 col n (hi)       (r/z dot)
//  f[24..31] : K5[m][n], m in lo?0..7:8..15        (hc partial)
//  f[32]     : u0[n] (lo) / u2[n] (hi)
//  f[33]     : bh[n]/2  (both halves; halves sum across the xor)
//  f[34]     : u4[n]/2  (both halves)
//  f[35]     : pad
// Storage: blob[t][g][L] as float4, g = f>>2 (0..8), L = 0..31.
// Padded +2 steps so the tail prefetches (t+2, t+3 past the end) stay in
// bounds; those values are loaded but never used.
__device__ float g_blob[(size_t)(T_STEPS + 2) * 1152];

#define BIDX(ln, f) ((((f) >> 2) * 128) + ((ln) * 4) + ((f) & 3))

__device__ __forceinline__ float tanha(float x){
    float y; asm("tanh.approx.f32 %0, %1;" : "=f"(y) : "f"(x)); return y;
}
__device__ __forceinline__ float sigm(float x){ return fmaf(0.5f, tanha(0.5f * x), 0.5f); }

// ---------------------------------------------------------------------------
// Precompute kernel: one warp per timestep. (Identical to R10.)
// ---------------------------------------------------------------------------
__global__ void __launch_bounds__(128) precompute_kernel(
    const float* __restrict__ inputs, const float* __restrict__ a_list,
    const float* __restrict__ gcn_wx, const float* __restrict__ gcn_bx,
    const float* __restrict__ gcn_wh, const float* __restrict__ gcn_bh,
    const float* __restrict__ gru_k,  const float* __restrict__ gru_b)
{
    __shared__ float Lh[3][16][16];
    __shared__ float Lsum[16][16];
    __shared__ float dd[3][16], dis[3][16];
    __shared__ float Qh[4][256];
    __shared__ float bs[4][1152];
    __shared__ float xsc[4][80];

    int tid = threadIdx.x;

    if (tid < 48) {
        int l = tid / 16, j = tid % 16;
        float s = 0.0f;
        #pragma unroll
        for (int i = 0; i < 16; i++) s += a_list[l*256 + i*16 + j];
        dd[l][j] = s;
        dis[l][j] = rsqrtf(s);
    }
    __syncthreads();
    for (int e = tid; e < 768; e += 128) {
        int l = e / 256, rc = e % 256, i = rc / 16, j = rc % 16;
        float Lv = ((i == j) ? dd[l][i] : 0.0f) - a_list[e];
        Lh[l][i][j] = Lv * dis[l][i] * dis[l][j];
    }
    __syncthreads();
    {
        float* LsF = &Lsum[0][0];
        float* LhF = &Lh[0][0][0];
        for (int e = tid; e < 256; e += 128)
            LsF[e] = LhF[e] + LhF[256 + e] + LhF[512 + e];
    }
    __syncthreads();

    int w = tid >> 5, lane = tid & 31;
    int t = blockIdx.x * 4 + w;

    float* LsF = &Lsum[0][0];
    float* LhF = &Lh[0][0][0];

    // zero staging
    for (int i = lane; i < 1152; i += 32) bs[w][i] = 0.0f;
    __syncwarp();

    // ---- h-GCN matrix A ----
    const float* wh = gcn_wh + t * 13;
    float wh0 = wh[0], wh1 = wh[1], wh2 = wh[2];
    float wh10 = wh[10], wh11 = wh[11], wh12 = wh[12];

    for (int e = lane; e < 256; e += 32)
        Qh[w][e] = wh0*LhF[e] + wh1*LhF[256+e] + wh2*LhF[512+e];
    __syncwarp();

    float cA1 = wh0 * wh11, cA2 = wh0 * wh12;
    for (int e = lane; e < 256; e += 32) {
        int n = e >> 4, m = e & 15;
        float ql = 0.0f;
        #pragma unroll
        for (int k = 0; k < 16; k++) ql += Qh[w][n*16 + k] * LsF[k*16 + m];
        float Av = ((n == m) ? wh10 : 0.0f) + cA1 * LsF[e] + cA2 * ql;
        if (t == 0) Av = 0.0f;
        int ln = (m < 8) ? n : 16 + n;
        bs[w][BIDX(ln, m & 7)] = Av;
    }

    // ---- x-GCN -> xg ----
    const float* wx  = gcn_wx + t * 26;
    const float* xin = inputs + t * 32;
    {
        int c = lane >> 4, k = lane & 15;
        float s = 0.0f;
        #pragma unroll
        for (int m = 0; m < 16; m++) s += LsF[k*16 + m] * xin[m*2 + c];
        xsc[w][lane] = s;
    }
    __syncwarp();
    {
        int c = lane >> 4, n = lane & 15;
        float wc0 = wx[c*13], wc1 = wx[c*13 + 1], wc2 = wx[c*13 + 2];
        float g = 0.0f;
        #pragma unroll
        for (int k = 0; k < 16; k++)
            g += (wc0*Lh[0][n][k] + wc1*Lh[1][n][k] + wc2*Lh[2][n][k]) * xsc[w][c*16 + k];
        float part = wx[c*13 + 10] * xin[n*2 + c]
                   + wx[c*13 + 11] * wc0 * xsc[w][c*16 + n]
                   + wx[c*13 + 12] * wc0 * g;
        xsc[w][32 + lane] = part;
    }
    __syncwarp();
    if (lane < 16) {
        float xg = xsc[w][32 + lane] + xsc[w][48 + lane] + gcn_bx[t*16 + lane];
        xsc[w][64 + lane] = fmaxf(xg, 0.0f);
    }
    __syncwarp();

    // ---- u vectors ----
    const float* gk = gru_k + (size_t)t * 1536;
    const float* gb = gru_b + t * 96;
    for (int e = lane; e < 48; e += 32) {
        int i2 = e >> 4, j = e & 15;
        const float* Kb = gk + i2 * 512;
        float u = gb[i2*32 + j] + gb[i2*32 + 16 + j];
        #pragma unroll
        for (int m = 0; m < 16; m++) u += xsc[w][64 + m] * Kb[m*16 + j];
        if (i2 == 0)      bs[w][BIDX(j, 32)] = u;
        else if (i2 == 1) bs[w][BIDX(16 + j, 32)] = u;
        else { bs[w][BIDX(j, 34)] = 0.5f*u; bs[w][BIDX(16 + j, 34)] = 0.5f*u; }
    }

    // ---- K1/K3/K5 columns ----
    for (int e = lane; e < 768; e += 32) {
        int which = e >> 8, rc = e & 255, m = rc >> 4, nn = rc & 15;
        float kv = gk[(2*which + 1)*256 + m*16 + nn];
        int ln, f;
        if (which == 0)      { ln = nn;                        f = 8 + m; }
        else if (which == 1) { ln = 16 + nn;                   f = 8 + m; }
        else                 { ln = (m < 8) ? nn : 16 + nn;    f = 24 + (m & 7); }
        bs[w][BIDX(ln, f)] = kv;
    }

    // ---- bh/2 (both halves) ----
    if (lane < 16) {
        float bh = (t == 0) ? 0.0f : gcn_bh[t*16 + lane];
        bs[w][BIDX(lane, 33)] = 0.5f*bh;
        bs[w][BIDX(16 + lane, 33)] = 0.5f*bh;
    }
    __syncwarp();

    float4* dst = reinterpret_cast<float4*>(g_blob + (size_t)t * 1152);
    const float4* srcv = reinterpret_cast<const float4*>(bs[w]);
    for (int i = lane; i < 288; i += 32) dst[i] = srcv[i];
}

// ---------------------------------------------------------------------------
// Recurrence kernel: warp 0 = consumer (sync-free; volatile-pinned LDG
// double-buffering straight from L2), warp 1 = L2 prefetcher.
// No ring, no producer, no polls.
// ---------------------------------------------------------------------------

// Predicated global store: no BSSY/BSYNC.
__device__ __forceinline__ void st_pred(float* p, float v, uint32_t pred){
    asm volatile("{\n\t.reg .pred q;\n\tsetp.ne.u32 q, %2, 0;\n\t@q st.global.f32 [%0], %1;\n\t}"
                 :: "l"(p), "f"(v), "r"(pred) : "memory");
}

__device__ __forceinline__ void sts_f32(uint32_t a, float v){
    asm volatile("st.volatile.shared.f32 [%0], %1;" :: "r"(a), "f"(v));
}
__device__ __forceinline__ void lds_v4(float* d, uint32_t a){
    asm volatile("ld.volatile.shared.v4.f32 {%0,%1,%2,%3}, [%4];"
                 : "=f"(d[0]),"=f"(d[1]),"=f"(d[2]),"=f"(d[3]) : "r"(a));
}

// Volatile LDG.128: pinned issue position (cannot be sunk to use like R5's
// __ldg), completion tracked by scoreboard at the register use ~1 step later.
#define LOADG(dst, ptr)                                                      \
    {                                                                        \
        _Pragma("unroll")                                                    \
        for (int _j = 0; _j < 9; _j++) {                                     \
            asm volatile("ld.global.nc.v4.f32 {%0,%1,%2,%3}, [%4];"          \
                : "=f"((dst)[4*_j]), "=f"((dst)[4*_j+1]),                    \
                  "=f"((dst)[4*_j+2]), "=f"((dst)[4*_j+3])                   \
                : "l"((ptr) + _j * 32));                                     \
        }                                                                    \
    }

// R10 gru_step, unchanged: smem exchanges for all broadcasts, two shfl_xor
// cross-half hops, folded biases, predicated output store.
__device__ __forceinline__ void gru_step(const float (&w)[36], float (&hv)[8],
                                         float* __restrict__ out, int t,
                                         uint32_t hip,
                                         uint32_t hgb, uint32_t hgslot,
                                         uint32_t rhslot, uint32_t rhread,
                                         uint32_t hb, uint32_t hslot, uint32_t hread)
{
    // hg = relu(A@h + bh), split across halves; bh/2 folded into each half
    float a0 = fmaf(w[0], hv[0], w[33]);
    float a1 = w[1]*hv[1];
    a0 = fmaf(w[2], hv[2], a0); a1 = fmaf(w[3], hv[3], a1);
    a0 = fmaf(w[4], hv[4], a0); a1 = fmaf(w[5], hv[5], a1);
    a0 = fmaf(w[6], hv[6], a0); a1 = fmaf(w[7], hv[7], a1);
    float pa = a0 + a1;
    pa += __shfl_xor_sync(FULLMASK, pa, 16);
    float hg = fmaxf(pa, 0.0f);

    // hg exchange: 1 STS + 4 LDS.128 (lanes n and n+16 write same value)
    float hgv[16];
    sts_f32(hgslot, hg);
    lds_v4(hgv + 0,  hgb);
    lds_v4(hgv + 4,  hgb + 16);
    lds_v4(hgv + 8,  hgb + 32);
    lds_v4(hgv + 12, hgb + 48);

    // r (lo) / z (hi) dot
    float v0 = w[32], v1 = 0.0f;
    #pragma unroll
    for (int m = 0; m < 16; m += 2) {
        v0 = fmaf(hgv[m],   w[8 + m], v0);
        v1 = fmaf(hgv[m+1], w[9 + m], v1);
    }
    float s = sigm(v0 + v1);
    float rh = s * hg;     // meaningful in lo lanes (r*hg)

    // rh exchange: STS to per-lane slot; lo lanes read rhbuf[0..7], hi [8..15]
    float rhv[8];
    sts_f32(rhslot, rh);
    lds_v4(rhv + 0, rhread);
    lds_v4(rhv + 4, rhread + 16);

    // hc partial, split across halves; u4/2 folded into each half
    float p0 = fmaf(rhv[0], w[24], w[34]);
    float p1 = rhv[1]*w[25];
    p0 = fmaf(rhv[2], w[26], p0); p1 = fmaf(rhv[3], w[27], p1);
    p0 = fmaf(rhv[4], w[28], p0); p1 = fmaf(rhv[5], w[29], p1);
    p0 = fmaf(rhv[6], w[30], p0); p1 = fmaf(rhv[7], w[31], p1);
    float p = p0 + p1;
    p += __shfl_xor_sync(FULLMASK, p, 16);
    float hc = tanha(p);
    float hn = fmaf(s, hg - hc, hc);      // meaningful in hi lanes (s = z)

    // h exchange: STS to per-lane slot; read own m-half from hi-lane copies
    sts_f32(hslot, hn);
    lds_v4(hv + 0, hread);
    lds_v4(hv + 4, hread + 16);

    // predicated store, off the critical chain
    st_pred(out + t * 16 + (threadIdx.x & 15), hn, hip);
}

__global__ void __launch_bounds__(64, 1) recurrent_kernel(float* __restrict__ out)
{
    __shared__ __align__(16) float hgbuf[16];
    __shared__ __align__(16) float rhbuf[32];
    __shared__ __align__(16) float hbuf[32];

    int tid = threadIdx.x;
    int w = tid >> 5, lane = tid & 31;

    if (w == 0) {
        // ---------------- consumer (sync-free) ----------------
        uint32_t hip = (lane >= 16) ? 1u : 0u;
        uint32_t hgb = (uint32_t)__cvta_generic_to_shared(hgbuf);
        uint32_t hgslot = hgb + ((uint32_t)(lane & 15) << 2);
        uint32_t rhb = (uint32_t)__cvta_generic_to_shared(rhbuf);
        uint32_t rhslot = rhb + ((uint32_t)lane << 2);
        uint32_t rhread = rhb + (hip ? 32u : 0u);      // rhbuf[8..15] : [0..7]
        uint32_t hb  = (uint32_t)__cvta_generic_to_shared(hbuf);
        uint32_t hslot = hb + ((uint32_t)lane << 2);
        uint32_t hread = hb + (hip ? 96u : 64u);       // hbuf[24..31] : [16..23]

        float hv[8];
        #pragma unroll
        for (int j = 0; j < 8; j++) hv[j] = 0.0f;

        const float4* blob4 = reinterpret_cast<const float4*>(g_blob);
        const float4* pa = blob4 + lane;               // step 0
        const float4* pb = blob4 + 288 + lane;         // step 1

        float wa[36], wb[36];
        LOADG(wa, pa);
        LOADG(wb, pb);

        #pragma unroll 1
        for (int t = 0; t < T_STEPS; t += 2) {
            gru_step(wa, hv, out, t, hip, hgb, hgslot, rhslot, rhread, hb, hslot, hread);

            pa += 576;                                  // step t+2
            LOADG(wa, pa);

            gru_step(wb, hv, out, t + 1, hip, hgb, hgslot, rhslot, rhread, hb, hslot, hread);

            pb += 576;                                  // step t+3
            LOADG(wb, pb);
        }
    } else {
        // ---------------- L2 prefetcher ----------------
        const char* p = reinterpret_cast<const char*>(g_blob);
        size_t total = (size_t)T_STEPS * 4608;
        #pragma unroll 4
        for (size_t off = (size_t)lane * 128; off < total; off += 4096) {
            asm volatile("prefetch.global.L2 [%0];" :: "l"(p + off));
        }
    }
}

extern "C" void kernel_launch(void* const* d_in, const int* in_sizes, int n_in,
                              void* d_out, int out_size)
{
    const float* inputs = (const float*)d_in[0];
    const float* a_list = (const float*)d_in[1];
    const float* gcn_wx = (const float*)d_in[2];
    const float* gcn_bx = (const float*)d_in[3];
    const float* gcn_wh = (const float*)d_in[4];
    const float* gcn_bh = (const float*)d_in[5];
    const float* gru_k  = (const float*)d_in[6];
    const float* gru_b  = (const float*)d_in[7];

    precompute_kernel<<<4096, 128>>>(inputs, a_list, gcn_wx, gcn_bx,
                                     gcn_wh, gcn_bh, gru_k, gru_b);
    recurrent_kernel<<<1, 64>>>((float*)d_out);
}

// round 14
// speedup vs baseline: 1.7655x; 1.7655x over previous
#include <cuda_runtime.h>
#include <cstdint>

#define T_STEPS 16384
#define RING 8
#define FULLMASK 0xffffffffu

// Per-step blob, 36 floats per lane (32 lanes) = 1152 floats = 4608 B/step.
// Lane L (n = L&15, hi = L>=16):
//  f[0..7]   : A[n][m] for m in lo?0..7:8..15      (hg partial)
//  f[8..23]  : K1 col n (lo) / K3 col n (hi)       (r/z dot)
//  f[24..31] : K5[m][n], m in lo?0..7:8..15        (hc partial)
//  f[32]     : u0[n] (lo) / u2[n] (hi)
//  f[33]     : bh[n]/2  (both halves; halves sum across the xor)
//  f[34]     : u4[n]/2  (both halves)
//  f[35]     : pad
// Storage: blob[t][g][L] as float4, g = f>>2 (0..8), L = 0..31.
__device__ float g_blob[(size_t)T_STEPS * 1152];

#define BIDX(ln, f) ((((f) >> 2) * 128) + ((ln) * 4) + ((f) & 3))

__device__ __forceinline__ float tanha(float x){
    float y; asm("tanh.approx.f32 %0, %1;" : "=f"(y) : "f"(x)); return y;
}
__device__ __forceinline__ float sigm(float x){ return fmaf(0.5f, tanha(0.5f * x), 0.5f); }

// ---------------------------------------------------------------------------
// Precompute kernel: one warp per timestep. (Identical to R10.)
// ---------------------------------------------------------------------------
__global__ void __launch_bounds__(128) precompute_kernel(
    const float* __restrict__ inputs, const float* __restrict__ a_list,
    const float* __restrict__ gcn_wx, const float* __restrict__ gcn_bx,
    const float* __restrict__ gcn_wh, const float* __restrict__ gcn_bh,
    const float* __restrict__ gru_k,  const float* __restrict__ gru_b)
{
    __shared__ float Lh[3][16][16];
    __shared__ float Lsum[16][16];
    __shared__ float dd[3][16], dis[3][16];
    __shared__ float Qh[4][256];
    __shared__ float bs[4][1152];
    __shared__ float xsc[4][80];

    int tid = threadIdx.x;

    if (tid < 48) {
        int l = tid / 16, j = tid % 16;
        float s = 0.0f;
        #pragma unroll
        for (int i = 0; i < 16; i++) s += a_list[l*256 + i*16 + j];
        dd[l][j] = s;
        dis[l][j] = rsqrtf(s);
    }
    __syncthreads();
    for (int e = tid; e < 768; e += 128) {
        int l = e / 256, rc = e % 256, i = rc / 16, j = rc % 16;
        float Lv = ((i == j) ? dd[l][i] : 0.0f) - a_list[e];
        Lh[l][i][j] = Lv * dis[l][i] * dis[l][j];
    }
    __syncthreads();
    {
        float* LsF = &Lsum[0][0];
        float* LhF = &Lh[0][0][0];
        for (int e = tid; e < 256; e += 128)
            LsF[e] = LhF[e] + LhF[256 + e] + LhF[512 + e];
    }
    __syncthreads();

    int w = tid >> 5, lane = tid & 31;
    int t = blockIdx.x * 4 + w;

    float* LsF = &Lsum[0][0];
    float* LhF = &Lh[0][0][0];

    // zero staging
    for (int i = lane; i < 1152; i += 32) bs[w][i] = 0.0f;
    __syncwarp();

    // ---- h-GCN matrix A ----
    const float* wh = gcn_wh + t * 13;
    float wh0 = wh[0], wh1 = wh[1], wh2 = wh[2];
    float wh10 = wh[10], wh11 = wh[11], wh12 = wh[12];

    for (int e = lane; e < 256; e += 32)
        Qh[w][e] = wh0*LhF[e] + wh1*LhF[256+e] + wh2*LhF[512+e];
    __syncwarp();

    float cA1 = wh0 * wh11, cA2 = wh0 * wh12;
    for (int e = lane; e < 256; e += 32) {
        int n = e >> 4, m = e & 15;
        float ql = 0.0f;
        #pragma unroll
        for (int k = 0; k < 16; k++) ql += Qh[w][n*16 + k] * LsF[k*16 + m];
        float Av = ((n == m) ? wh10 : 0.0f) + cA1 * LsF[e] + cA2 * ql;
        if (t == 0) Av = 0.0f;
        int ln = (m < 8) ? n : 16 + n;
        bs[w][BIDX(ln, m & 7)] = Av;
    }

    // ---- x-GCN -> xg ----
    const float* wx  = gcn_wx + t * 26;
    const float* xin = inputs + t * 32;
    {
        int c = lane >> 4, k = lane & 15;
        float s = 0.0f;
        #pragma unroll
        for (int m = 0; m < 16; m++) s += LsF[k*16 + m] * xin[m*2 + c];
        xsc[w][lane] = s;
    }
    __syncwarp();
    {
        int c = lane >> 4, n = lane & 15;
        float wc0 = wx[c*13], wc1 = wx[c*13 + 1], wc2 = wx[c*13 + 2];
        float g = 0.0f;
        #pragma unroll
        for (int k = 0; k < 16; k++)
            g += (wc0*Lh[0][n][k] + wc1*Lh[1][n][k] + wc2*Lh[2][n][k]) * xsc[w][c*16 + k];
        float part = wx[c*13 + 10] * xin[n*2 + c]
                   + wx[c*13 + 11] * wc0 * xsc[w][c*16 + n]
                   + wx[c*13 + 12] * wc0 * g;
        xsc[w][32 + lane] = part;
    }
    __syncwarp();
    if (lane < 16) {
        float xg = xsc[w][32 + lane] + xsc[w][48 + lane] + gcn_bx[t*16 + lane];
        xsc[w][64 + lane] = fmaxf(xg, 0.0f);
    }
    __syncwarp();

    // ---- u vectors ----
    const float* gk = gru_k + (size_t)t * 1536;
    const float* gb = gru_b + t * 96;
    for (int e = lane; e < 48; e += 32) {
        int i2 = e >> 4, j = e & 15;
        const float* Kb = gk + i2 * 512;
        float u = gb[i2*32 + j] + gb[i2*32 + 16 + j];
        #pragma unroll
        for (int m = 0; m < 16; m++) u += xsc[w][64 + m] * Kb[m*16 + j];
        if (i2 == 0)      bs[w][BIDX(j, 32)] = u;
        else if (i2 == 1) bs[w][BIDX(16 + j, 32)] = u;
        else { bs[w][BIDX(j, 34)] = 0.5f*u; bs[w][BIDX(16 + j, 34)] = 0.5f*u; }
    }

    // ---- K1/K3/K5 columns ----
    for (int e = lane; e < 768; e += 32) {
        int which = e >> 8, rc = e & 255, m = rc >> 4, nn = rc & 15;
        float kv = gk[(2*which + 1)*256 + m*16 + nn];
        int ln, f;
        if (which == 0)      { ln = nn;                        f = 8 + m; }
        else if (which == 1) { ln = 16 + nn;                   f = 8 + m; }
        else                 { ln = (m < 8) ? nn : 16 + nn;    f = 24 + (m & 7); }
        bs[w][BIDX(ln, f)] = kv;
    }

    // ---- bh/2 (both halves) ----
    if (lane < 16) {
        float bh = (t == 0) ? 0.0f : gcn_bh[t*16 + lane];
        bs[w][BIDX(lane, 33)] = 0.5f*bh;
        bs[w][BIDX(16 + lane, 33)] = 0.5f*bh;
    }
    __syncwarp();

    float4* dst = reinterpret_cast<float4*>(g_blob + (size_t)t * 1152);
    const float4* srcv = reinterpret_cast<const float4*>(bs[w]);
    for (int i = lane; i < 288; i += 32) dst[i] = srcv[i];
}

// ---------------------------------------------------------------------------
// Recurrence kernel (R10 ring) with packed-f32x2 dots.
// ---------------------------------------------------------------------------
typedef unsigned long long ull;

__device__ __forceinline__ int ldacq(uint32_t a){
    int v; asm volatile("ld.acquire.cta.shared::cta.b32 %0, [%1];" : "=r"(v) : "r"(a)); return v;
}
__device__ __forceinline__ void st_pred(float* p, float v, uint32_t pred){
    asm volatile("{\n\t.reg .pred q;\n\tsetp.ne.u32 q, %2, 0;\n\t@q st.global.f32 [%0], %1;\n\t}"
                 :: "l"(p), "f"(v), "r"(pred) : "memory");
}
__device__ __forceinline__ void sts_f32(uint32_t a, float v){
    asm volatile("st.volatile.shared.f32 [%0], %1;" :: "r"(a), "f"(v));
}
// 128-bit shared load into two packed-f32x2 (b64) registers.
__device__ __forceinline__ void lds_2b64(ull* d, uint32_t a){
    asm volatile("ld.volatile.shared.v2.b64 {%0,%1}, [%2];"
                 : "=l"(d[0]),"=l"(d[1]) : "r"(a));
}

#define MUL2(out, a, b) asm("mul.rn.f32x2 %0, %1, %2;" : "=l"(out) : "l"(a), "l"(b))
#define FMA2(acc, a, b) asm("fma.rn.f32x2 %0, %1, %2, %3;" : "=l"(acc) : "l"(a), "l"(b), "l"(acc))
#define ADD2(out, a, b) asm("add.rn.f32x2 %0, %1, %2;" : "=l"(out) : "l"(a), "l"(b))
#define UNPACK2(lo, hi, v) asm("mov.b64 {%0,%1}, %2;" : "=f"(lo), "=f"(hi) : "l"(v))

// Weights as 18 b64 pairs: w2[k] = {f[2k], f[2k+1]}.
// w2[0..3]=A half-row, w2[4..11]=K1/K3 col, w2[12..15]=K5 half-col,
// w2[16]={u0, bh/2}, w2[17]={u4/2, pad}.
__device__ __forceinline__ void gru_step(const ull (&w)[18], ull (&hv2)[4],
                                         float* __restrict__ out, int t,
                                         uint32_t hip,
                                         uint32_t hgb, uint32_t hgslot,
                                         uint32_t rhslot, uint32_t rhread,
                                         uint32_t hslot, uint32_t hread)
{
    float u0, bh2, u42, padf;
    UNPACK2(u0, bh2, w[16]);
    UNPACK2(u42, padf, w[17]);

    // hg = relu(A@h + bh): packed half-dot, bh/2 folded per half (sums via xor)
    ull ac0, ac1;
    MUL2(ac0, w[0], hv2[0]); MUL2(ac1, w[1], hv2[1]);
    FMA2(ac0, w[2], hv2[2]); FMA2(ac1, w[3], hv2[3]);
    ADD2(ac0, ac0, ac1);
    float alo, ahi; UNPACK2(alo, ahi, ac0);
    float pa = (alo + ahi) + bh2;
    pa += __shfl_xor_sync(FULLMASK, pa, 16);
    float hg = fmaxf(pa, 0.0f);

    // hg exchange: 1 STS + 4 LDS.128 -> 8 packed pairs
    ull hgv2[8];
    sts_f32(hgslot, hg);
    lds_2b64(hgv2 + 0, hgb);
    lds_2b64(hgv2 + 2, hgb + 16);
    lds_2b64(hgv2 + 4, hgb + 32);
    lds_2b64(hgv2 + 6, hgb + 48);

    // r (lo) / z (hi): full 16-wide packed dot
    ull v0, v1;
    MUL2(v0, w[4], hgv2[0]); MUL2(v1, w[5], hgv2[1]);
    FMA2(v0, w[6], hgv2[2]); FMA2(v1, w[7], hgv2[3]);
    FMA2(v0, w[8], hgv2[4]); FMA2(v1, w[9], hgv2[5]);
    FMA2(v0, w[10], hgv2[6]); FMA2(v1, w[11], hgv2[7]);
    ADD2(v0, v0, v1);
    float vlo, vhi; UNPACK2(vlo, vhi, v0);
    float s = sigm((vlo + vhi) + u0);
    float rh = s * hg;     // meaningful in lo lanes (r*hg)

    // rh exchange: STS; lo lanes read rhbuf[0..7], hi [8..15]
    ull rhv2[4];
    sts_f32(rhslot, rh);
    lds_2b64(rhv2 + 0, rhread);
    lds_2b64(rhv2 + 2, rhread + 16);

    // hc: packed half-dot, u4/2 folded per half
    ull p0, p1;
    MUL2(p0, w[12], rhv2[0]); MUL2(p1, w[13], rhv2[1]);
    FMA2(p0, w[14], rhv2[2]); FMA2(p1, w[15], rhv2[3]);
    ADD2(p0, p0, p1);
    float plo, phi; UNPACK2(plo, phi, p0);
    float p = (plo + phi) + u42;
    p += __shfl_xor_sync(FULLMASK, p, 16);
    float hc = tanha(p);
    float hn = fmaf(s, hg - hc, hc);      // meaningful in hi lanes (s = z)

    // h exchange: STS; read own m-half from hi-lane copies
    sts_f32(hslot, hn);
    lds_2b64(hv2 + 0, hread);
    lds_2b64(hv2 + 2, hread + 16);

    // predicated store, off the critical chain
    st_pred(out + t * 16 + (threadIdx.x & 15), hn, hip);
}

#define LOADW(dst, slot)                                                     \
    {                                                                        \
        const ulonglong2* _s =                                               \
            reinterpret_cast<const ulonglong2*>(&ring[(slot) * 288 + lane]); \
        ulonglong2* _d = reinterpret_cast<ulonglong2*>(dst);                 \
        _Pragma("unroll")                                                    \
        for (int _j = 0; _j < 9; _j++) _d[_j] = _s[_j * 32];                 \
    }

__global__ void __launch_bounds__(128) recurrent_kernel(float* __restrict__ out)
{
    __shared__ float4 ring[RING * 288];
    __shared__ __align__(16) float hgbuf[16];
    __shared__ __align__(16) float rhbuf[32];
    __shared__ __align__(16) float hbuf[32];
    __shared__ int Wsh;
    __shared__ int cons_prog;

    int tid = threadIdx.x;
    if (tid == 0) { Wsh = 0; cons_prog = 0; }
    __syncthreads();

    int w = tid >> 5, lane = tid & 31;

    if (w == 0) {
        // ---------------- consumer ----------------
        uint32_t hip = (lane >= 16) ? 1u : 0u;
        uint32_t hgb = (uint32_t)__cvta_generic_to_shared(hgbuf);
        uint32_t hgslot = hgb + ((uint32_t)(lane & 15) << 2);
        uint32_t rhb = (uint32_t)__cvta_generic_to_shared(rhbuf);
        uint32_t rhslot = rhb + ((uint32_t)lane << 2);
        uint32_t rhread = rhb + (hip ? 32u : 0u);      // rhbuf[8..15] : [0..7]
        uint32_t hb  = (uint32_t)__cvta_generic_to_shared(hbuf);
        uint32_t hslot = hb + ((uint32_t)lane << 2);
        uint32_t hread = hb + (hip ? 96u : 64u);       // hbuf[24..31] : [16..23]

        ull hv2[4];
        #pragma unroll
        for (int j = 0; j < 4; j++) hv2[j] = 0ull;

        uint32_t Wa = (uint32_t)__cvta_generic_to_shared(&Wsh);
        int Wloc = 0;

        ull wa[18], wb[18];
        while (Wloc < 1) Wloc = ldacq(Wa);
        LOADW(wa, 0);

        #pragma unroll 1
        for (int t = 0; t < T_STEPS; t += 2) {
            // poll for t+1 data (demand no earlier than needed)
            while (Wloc < t + 2) Wloc = ldacq(Wa);
            LOADW(wb, (t + 1) & (RING - 1));

            gru_step(wa, hv2, out, t, hip, hgb, hgslot, rhslot, rhread, hslot, hread);

            // poll for t+2 data at the midpoint (after step t's compute)
            if (t + 2 < T_STEPS) {
                while (Wloc < t + 3) Wloc = ldacq(Wa);
                LOADW(wa, (t + 2) & (RING - 1));
            }

            gru_step(wb, hv2, out, t + 1, hip, hgb, hgslot, rhslot, rhread, hslot, hread);

            // all lanes store same value to same address: no divergence
            *(volatile int*)&cons_prog = t + 2;
        }
    } else if (w == 1) {
        // ---------------- producer (single warp, monotonic watermark) ----
        // wait_group 2 lag: publish t-1 after commit t. Slack vs consumer = 3.
        uint32_t ringb = (uint32_t)__cvta_generic_to_shared(ring);
        uint32_t Wa = (uint32_t)__cvta_generic_to_shared(&Wsh);
        const float4* blob4 = reinterpret_cast<const float4*>(g_blob);

        for (int t = 0; t < T_STEPS; t++) {
            if (t >= RING) {
                while (*(volatile int*)&cons_prog < t - RING + 1) __nanosleep(32);
            }
            const float4* src = blob4 + (size_t)t * 288 + lane;
            uint32_t dst = ringb + ((uint32_t)(t & (RING - 1)) * 288 + lane) * 16;
            #pragma unroll
            for (int j = 0; j < 9; j++) {
                asm volatile("cp.async.cg.shared.global [%0], [%1], 16;"
                             :: "r"(dst + j * 512), "l"(src + j * 32) : "memory");
            }
            asm volatile("cp.async.commit_group;" ::: "memory");
            asm volatile("cp.async.wait_group 2;" ::: "memory");
            __threadfence_block();
            __syncwarp();
            if (lane == 0 && t >= 2) {
                asm volatile("st.release.cta.shared::cta.b32 [%0], %1;"
                             :: "r"(Wa), "r"(t - 1) : "memory");
            }
        }
        asm volatile("cp.async.wait_group 0;" ::: "memory");
        __threadfence_block();
        __syncwarp();
        if (lane == 0) {
            asm volatile("st.release.cta.shared::cta.b32 [%0], %1;"
                         :: "r"(Wa), "r"(T_STEPS + RING) : "memory");
        }
    } else if (w == 2) {
        // ---------------- L2 prefetcher ----------------
        const char* p = reinterpret_cast<const char*>(g_blob);
        size_t total = (size_t)T_STEPS * 4608;
        #pragma unroll 4
        for (size_t off = (size_t)lane * 128; off < total; off += 4096) {
            asm volatile("prefetch.global.L2 [%0];" :: "l"(p + off));
        }
    }
}

extern "C" void kernel_launch(void* const* d_in, const int* in_sizes, int n_in,
                              void* d_out, int out_size)
{
    const float* inputs = (const float*)d_in[0];
    const float* a_list = (const float*)d_in[1];
    const float* gcn_wx = (const float*)d_in[2];
    const float* gcn_bx = (const float*)d_in[3];
    const float* gcn_wh = (const float*)d_in[4];
    const float* gcn_bh = (const float*)d_in[5];
    const float* gru_k  = (const float*)d_in[6];
    const float* gru_b  = (const float*)d_in[7];

    precompute_kernel<<<4096, 128>>>(inputs, a_list, gcn_wx, gcn_bx,
                                     gcn_wh, gcn_bh, gru_k, gru_b);
    recurrent_kernel<<<1, 128>>>((float*)d_out);
}

// round 15
// speedup vs baseline: 1.9107x; 1.0823x over previous
#include <cuda_runtime.h>
#include <cstdint>

#define T_STEPS 16384
#define RING 8
#define FULLMASK 0xffffffffu

// Per-step blob, 36 floats per lane (32 lanes) = 1152 floats = 4608 B/step.
// Lane L (n = L&15, hi = L>=16):
//  f[0..7]   : A[n][m] for m in lo?0..7:8..15      (hg partial)
//  f[8..23]  : K1 col n / 2 (lo) / K3 col n / 2 (hi)   (r/z dot, sigm-folded)
//  f[24..31] : K5[m][n], m in lo?0..7:8..15        (hc partial)
//  f[32]     : u0[n]/2 (lo) / u2[n]/2 (hi)         (sigm-folded)
//  f[33]     : bh[n]/2  (both halves; halves sum across the xor)
//  f[34]     : u4[n]/2  (both halves)
//  f[35]     : pad
// Storage: blob[t][g][L] as float4, g = f>>2 (0..8), L = 0..31.
__device__ float g_blob[(size_t)T_STEPS * 1152];

#define BIDX(ln, f) ((((f) >> 2) * 128) + ((ln) * 4) + ((f) & 3))

__device__ __forceinline__ float tanha(float x){
    float y; asm("tanh.approx.f32 %0, %1;" : "=f"(y) : "f"(x)); return y;
}

// ---------------------------------------------------------------------------
// Precompute kernel: one warp per timestep. (R10 + 0.5-folding for sigm.)
// ---------------------------------------------------------------------------
__global__ void __launch_bounds__(128) precompute_kernel(
    const float* __restrict__ inputs, const float* __restrict__ a_list,
    const float* __restrict__ gcn_wx, const float* __restrict__ gcn_bx,
    const float* __restrict__ gcn_wh, const float* __restrict__ gcn_bh,
    const float* __restrict__ gru_k,  const float* __restrict__ gru_b)
{
    __shared__ float Lh[3][16][16];
    __shared__ float Lsum[16][16];
    __shared__ float dd[3][16], dis[3][16];
    __shared__ float Qh[4][256];
    __shared__ float bs[4][1152];
    __shared__ float xsc[4][80];

    int tid = threadIdx.x;

    if (tid < 48) {
        int l = tid / 16, j = tid % 16;
        float s = 0.0f;
        #pragma unroll
        for (int i = 0; i < 16; i++) s += a_list[l*256 + i*16 + j];
        dd[l][j] = s;
        dis[l][j] = rsqrtf(s);
    }
    __syncthreads();
    for (int e = tid; e < 768; e += 128) {
        int l = e / 256, rc = e % 256, i = rc / 16, j = rc % 16;
        float Lv = ((i == j) ? dd[l][i] : 0.0f) - a_list[e];
        Lh[l][i][j] = Lv * dis[l][i] * dis[l][j];
    }
    __syncthreads();
    {
        float* LsF = &Lsum[0][0];
        float* LhF = &Lh[0][0][0];
        for (int e = tid; e < 256; e += 128)
            LsF[e] = LhF[e] + LhF[256 + e] + LhF[512 + e];
    }
    __syncthreads();

    int w = tid >> 5, lane = tid & 31;
    int t = blockIdx.x * 4 + w;

    float* LsF = &Lsum[0][0];
    float* LhF = &Lh[0][0][0];

    // zero staging
    for (int i = lane; i < 1152; i += 32) bs[w][i] = 0.0f;
    __syncwarp();

    // ---- h-GCN matrix A ----
    const float* wh = gcn_wh + t * 13;
    float wh0 = wh[0], wh1 = wh[1], wh2 = wh[2];
    float wh10 = wh[10], wh11 = wh[11], wh12 = wh[12];

    for (int e = lane; e < 256; e += 32)
        Qh[w][e] = wh0*LhF[e] + wh1*LhF[256+e] + wh2*LhF[512+e];
    __syncwarp();

    float cA1 = wh0 * wh11, cA2 = wh0 * wh12;
    for (int e = lane; e < 256; e += 32) {
        int n = e >> 4, m = e & 15;
        float ql = 0.0f;
        #pragma unroll
        for (int k = 0; k < 16; k++) ql += Qh[w][n*16 + k] * LsF[k*16 + m];
        float Av = ((n == m) ? wh10 : 0.0f) + cA1 * LsF[e] + cA2 * ql;
        if (t == 0) Av = 0.0f;
        int ln = (m < 8) ? n : 16 + n;
        bs[w][BIDX(ln, m & 7)] = Av;
    }

    // ---- x-GCN -> xg ----
    const float* wx  = gcn_wx + t * 26;
    const float* xin = inputs + t * 32;
    {
        int c = lane >> 4, k = lane & 15;
        float s = 0.0f;
        #pragma unroll
        for (int m = 0; m < 16; m++) s += LsF[k*16 + m] * xin[m*2 + c];
        xsc[w][lane] = s;
    }
    __syncwarp();
    {
        int c = lane >> 4, n = lane & 15;
        float wc0 = wx[c*13], wc1 = wx[c*13 + 1], wc2 = wx[c*13 + 2];
        float g = 0.0f;
        #pragma unroll
        for (int k = 0; k < 16; k++)
            g += (wc0*Lh[0][n][k] + wc1*Lh[1][n][k] + wc2*Lh[2][n][k]) * xsc[w][c*16 + k];
        float part = wx[c*13 + 10] * xin[n*2 + c]
                   + wx[c*13 + 11] * wc0 * xsc[w][c*16 + n]
                   + wx[c*13 + 12] * wc0 * g;
        xsc[w][32 + lane] = part;
    }
    __syncwarp();
    if (lane < 16) {
        float xg = xsc[w][32 + lane] + xsc[w][48 + lane] + gcn_bx[t*16 + lane];
        xsc[w][64 + lane] = fmaxf(xg, 0.0f);
    }
    __syncwarp();

    // ---- u vectors (u0/u2 scaled by 0.5 for the sigm fold) ----
    const float* gk = gru_k + (size_t)t * 1536;
    const float* gb = gru_b + t * 96;
    for (int e = lane; e < 48; e += 32) {
        int i2 = e >> 4, j = e & 15;
        const float* Kb = gk + i2 * 512;
        float u = gb[i2*32 + j] + gb[i2*32 + 16 + j];
        #pragma unroll
        for (int m = 0; m < 16; m++) u += xsc[w][64 + m] * Kb[m*16 + j];
        if (i2 == 0)      bs[w][BIDX(j, 32)] = 0.5f*u;
        else if (i2 == 1) bs[w][BIDX(16 + j, 32)] = 0.5f*u;
        else { bs[w][BIDX(j, 34)] = 0.5f*u; bs[w][BIDX(16 + j, 34)] = 0.5f*u; }
    }

    // ---- K1/K3 (scaled by 0.5, sigm fold) / K5 columns ----
    for (int e = lane; e < 768; e += 32) {
        int which = e >> 8, rc = e & 255, m = rc >> 4, nn = rc & 15;
        float kv = gk[(2*which + 1)*256 + m*16 + nn];
        int ln, f;
        if (which == 0)      { ln = nn;                        f = 8 + m;  kv *= 0.5f; }
        else if (which == 1) { ln = 16 + nn;                   f = 8 + m;  kv *= 0.5f; }
        else                 { ln = (m < 8) ? nn : 16 + nn;    f = 24 + (m & 7); }
        bs[w][BIDX(ln, f)] = kv;
    }

    // ---- bh/2 (both halves) ----
    if (lane < 16) {
        float bh = (t == 0) ? 0.0f : gcn_bh[t*16 + lane];
        bs[w][BIDX(lane, 33)] = 0.5f*bh;
        bs[w][BIDX(16 + lane, 33)] = 0.5f*bh;
    }
    __syncwarp();

    float4* dst = reinterpret_cast<float4*>(g_blob + (size_t)t * 1152);
    const float4* srcv = reinterpret_cast<const float4*>(bs[w]);
    for (int i = lane; i < 288; i += 32) dst[i] = srcv[i];
}

// ---------------------------------------------------------------------------
// Recurrence kernel (R10 skeleton; 4-chain dots, folded sigm)
// ---------------------------------------------------------------------------
__device__ __forceinline__ int ldacq(uint32_t a){
    int v; asm volatile("ld.acquire.cta.shared::cta.b32 %0, [%1];" : "=r"(v) : "r"(a)); return v;
}
__device__ __forceinline__ void st_pred(float* p, float v, uint32_t pred){
    asm volatile("{\n\t.reg .pred q;\n\tsetp.ne.u32 q, %2, 0;\n\t@q st.global.f32 [%0], %1;\n\t}"
                 :: "l"(p), "f"(v), "r"(pred) : "memory");
}
__device__ __forceinline__ void sts_f32(uint32_t a, float v){
    asm volatile("st.volatile.shared.f32 [%0], %1;" :: "r"(a), "f"(v));
}
__device__ __forceinline__ void lds_v4(float* d, uint32_t a){
    asm volatile("ld.volatile.shared.v4.f32 {%0,%1,%2,%3}, [%4];"
                 : "=f"(d[0]),"=f"(d[1]),"=f"(d[2]),"=f"(d[3]) : "r"(a));
}

__device__ __forceinline__ void gru_step(const float (&w)[36], float (&hv)[8],
                                         float* __restrict__ out, int t,
                                         uint32_t hip,
                                         uint32_t hgb, uint32_t hgslot,
                                         uint32_t rhslot, uint32_t rhread,
                                         uint32_t hslot, uint32_t hread)
{
    // hg = relu(A@h + bh), half-split; bh/2 folded; 4 chains (depth 2)
    float a0 = fmaf(w[0], hv[0], w[33]);
    float a1 = w[1]*hv[1];
    float a2 = w[2]*hv[2];
    float a3 = w[3]*hv[3];
    a0 = fmaf(w[4], hv[4], a0); a1 = fmaf(w[5], hv[5], a1);
    a2 = fmaf(w[6], hv[6], a2); a3 = fmaf(w[7], hv[7], a3);
    float pa = (a0 + a1) + (a2 + a3);
    pa += __shfl_xor_sync(FULLMASK, pa, 16);
    float hg = fmaxf(pa, 0.0f);

    // hg exchange: 1 STS + 4 LDS.128 (lanes n and n+16 write same value)
    float hgv[16];
    sts_f32(hgslot, hg);
    lds_v4(hgv + 0,  hgb);
    lds_v4(hgv + 4,  hgb + 16);
    lds_v4(hgv + 8,  hgb + 32);
    lds_v4(hgv + 12, hgb + 48);

    // r (lo) / z (hi) dot; K/2 and u/2 pre-folded; 4 chains (depth 4)
    float v0 = fmaf(hgv[0], w[8],  w[32]);
    float v1 = hgv[1]*w[9];
    float v2 = hgv[2]*w[10];
    float v3 = hgv[3]*w[11];
    #pragma unroll
    for (int m = 4; m < 16; m += 4) {
        v0 = fmaf(hgv[m],   w[8 + m],  v0);
        v1 = fmaf(hgv[m+1], w[9 + m],  v1);
        v2 = fmaf(hgv[m+2], w[10 + m], v2);
        v3 = fmaf(hgv[m+3], w[11 + m], v3);
    }
    // sigm with folded input scale: s = 0.5*tanh(x/2) + 0.5, x/2 already in v
    float s = fmaf(0.5f, tanha((v0 + v1) + (v2 + v3)), 0.5f);
    float rh = s * hg;     // meaningful in lo lanes (r*hg)

    // rh exchange: STS; lo lanes read rhbuf[0..7], hi [8..15]
    float rhv[8];
    sts_f32(rhslot, rh);
    lds_v4(rhv + 0, rhread);
    lds_v4(rhv + 4, rhread + 16);

    // hc partial, half-split; u4/2 folded; 4 chains (depth 2)
    float p0 = fmaf(rhv[0], w[24], w[34]);
    float p1 = rhv[1]*w[25];
    float p2 = rhv[2]*w[26];
    float p3 = rhv[3]*w[27];
    p0 = fmaf(rhv[4], w[28], p0); p1 = fmaf(rhv[5], w[29], p1);
    p2 = fmaf(rhv[6], w[30], p2); p3 = fmaf(rhv[7], w[31], p3);
    float p = (p0 + p1) + (p2 + p3);
    p += __shfl_xor_sync(FULLMASK, p, 16);
    float hc = tanha(p);
    float hn = fmaf(s, hg - hc, hc);      // meaningful in hi lanes (s = z)

    // h exchange: STS; read own m-half from hi-lane copies
    sts_f32(hslot, hn);
    lds_v4(hv + 0, hread);
    lds_v4(hv + 4, hread + 16);

    // predicated store, off the critical chain
    st_pred(out + t * 16 + (threadIdx.x & 15), hn, hip);
}

#define LOADW(dst, slot)                                                     \
    {                                                                        \
        const float4* _s = &ring[(slot) * 288 + lane];                       \
        float4* _d = reinterpret_cast<float4*>(dst);                         \
        _Pragma("unroll")                                                    \
        for (int _j = 0; _j < 9; _j++) _d[_j] = _s[_j * 32];                 \
    }

__global__ void __launch_bounds__(128) recurrent_kernel(float* __restrict__ out)
{
    __shared__ float4 ring[RING * 288];
    __shared__ __align__(16) float hgbuf[16];
    __shared__ __align__(16) float rhbuf[32];
    __shared__ __align__(16) float hbuf[32];
    __shared__ int Wsh;
    __shared__ int cons_prog;

    int tid = threadIdx.x;
    if (tid == 0) { Wsh = 0; cons_prog = 0; }
    __syncthreads();

    int w = tid >> 5, lane = tid & 31;

    if (w == 0) {
        // ---------------- consumer ----------------
        uint32_t hip = (lane >= 16) ? 1u : 0u;
        uint32_t hgb = (uint32_t)__cvta_generic_to_shared(hgbuf);
        uint32_t hgslot = hgb + ((uint32_t)(lane & 15) << 2);
        uint32_t rhb = (uint32_t)__cvta_generic_to_shared(rhbuf);
        uint32_t rhslot = rhb + ((uint32_t)lane << 2);
        uint32_t rhread = rhb + (hip ? 32u : 0u);      // rhbuf[8..15] : [0..7]
        uint32_t hb  = (uint32_t)__cvta_generic_to_shared(hbuf);
        uint32_t hslot = hb + ((uint32_t)lane << 2);
        uint32_t hread = hb + (hip ? 96u : 64u);       // hbuf[24..31] : [16..23]

        float hv[8];
        #pragma unroll
        for (int j = 0; j < 8; j++) hv[j] = 0.0f;

        uint32_t Wa = (uint32_t)__cvta_generic_to_shared(&Wsh);
        int Wloc = 0;

        float wa[36], wb[36];
        while (Wloc < 1) Wloc = ldacq(Wa);
        LOADW(wa, 0);

        #pragma unroll 1
        for (int t = 0; t < T_STEPS; t += 2) {
            // poll for t+1 data (demand no earlier than needed)
            while (Wloc < t + 2) Wloc = ldacq(Wa);
            LOADW(wb, (t + 1) & (RING - 1));

            gru_step(wa, hv, out, t, hip, hgb, hgslot, rhslot, rhread, hslot, hread);

            // poll for t+2 data at the midpoint (after step t's compute)
            if (t + 2 < T_STEPS) {
                while (Wloc < t + 3) Wloc = ldacq(Wa);
                LOADW(wa, (t + 2) & (RING - 1));
            }

            gru_step(wb, hv, out, t + 1, hip, hgb, hgslot, rhslot, rhread, hslot, hread);

            // all lanes store same value to same address: no divergence
            *(volatile int*)&cons_prog = t + 2;
        }
    } else if (w == 1) {
        // ---------------- producer (single warp, monotonic watermark) ----
        // wait_group 2 lag: publish t-1 after commit t. Slack vs consumer = 3.
        uint32_t ringb = (uint32_t)__cvta_generic_to_shared(ring);
        uint32_t Wa = (uint32_t)__cvta_generic_to_shared(&Wsh);
        const float4* blob4 = reinterpret_cast<const float4*>(g_blob);

        for (int t = 0; t < T_STEPS; t++) {
            if (t >= RING) {
                while (*(volatile int*)&cons_prog < t - RING + 1) __nanosleep(32);
            }
            const float4* src = blob4 + (size_t)t * 288 + lane;
            uint32_t dst = ringb + ((uint32_t)(t & (RING - 1)) * 288 + lane) * 16;
            #pragma unroll
            for (int j = 0; j < 9; j++) {
                asm volatile("cp.async.cg.shared.global [%0], [%1], 16;"
                             :: "r"(dst + j * 512), "l"(src + j * 32) : "memory");
            }
            asm volatile("cp.async.commit_group;" ::: "memory");
            asm volatile("cp.async.wait_group 2;" ::: "memory");
            __threadfence_block();
            __syncwarp();
            if (lane == 0 && t >= 2) {
                asm volatile("st.release.cta.shared::cta.b32 [%0], %1;"
                             :: "r"(Wa), "r"(t - 1) : "memory");
            }
        }
        asm volatile("cp.async.wait_group 0;" ::: "memory");
        __threadfence_block();
        __syncwarp();
        if (lane == 0) {
            asm volatile("st.release.cta.shared::cta.b32 [%0], %1;"
                         :: "r"(Wa), "r"(T_STEPS + RING) : "memory");
        }
    } else if (w == 2) {
        // ---------------- L2 prefetcher ----------------
        const char* p = reinterpret_cast<const char*>(g_blob);
        size_t total = (size_t)T_STEPS * 4608;
        #pragma unroll 4
        for (size_t off = (size_t)lane * 128; off < total; off += 4096) {
            asm volatile("prefetch.global.L2 [%0];" :: "l"(p + off));
        }
    }
}

extern "C" void kernel_launch(void* const* d_in, const int* in_sizes, int n_in,
                              void* d_out, int out_size)
{
    const float* inputs = (const float*)d_in[0];
    const float* a_list = (const float*)d_in[1];
    const float* gcn_wx = (const float*)d_in[2];
    const float* gcn_bx = (const float*)d_in[3];
    const float* gcn_wh = (const float*)d_in[4];
    const float* gcn_bh = (const float*)d_in[5];
    const float* gru_k  = (const float*)d_in[6];
    const float* gru_b  = (const float*)d_in[7];

    precompute_kernel<<<4096, 128>>>(inputs, a_list, gcn_wx, gcn_bx,
                                     gcn_wh, gcn_bh, gru_k, gru_b);
    recurrent_kernel<<<1, 128>>>((float*)d_out);
}